// round 3
// baseline (speedup 1.0000x reference)
#include <cuda_runtime.h>

#define MB 128        // batch
#define KS 64         // slots
#define DD 8          // state dim
#define HH 128        // slot dim
#define MR (MB*KS)    // 8192 rows
#define NST 5         // rollout steps (min(T-1, 5) = 5, fixed by setup_inputs)
#define TT 6          // time steps in gt

// ---------------- device scratch (no allocations allowed) ----------------
__device__ float g_T3[MR*384];     // [H_self | a | b]
__device__ float g_r [MR*HH];      // mean_i relu(a_i + b_j + bias)
__device__ float g_S [MR*HH];      // slots
__device__ float g_Hu[MR*HH];      // hidden of upd MLP
__device__ float g_Hd[MR*HH];      // hidden of dec MLP
__device__ float g_He[MR*HH];      // hidden of enc MLP
__device__ float g_x0[MR*DD];      // gt[:,0] gathered
__device__ float g_Wc1[HH*384];    // [self_w1 | wi_a | wi_b]
__device__ float g_W2a[HH*HH];     // self_w2 @ upd_w1[:128]
__device__ float g_W2b[HH*HH];     // inter_w2 @ upd_w1[128:]
__device__ float g_W3 [HH*HH];     // upd_w2 @ dec_w1
__device__ float g_We2[HH*HH];     // aligned copy of enc_w2
__device__ float g_bc1[384];
__device__ float g_b2 [HH];
__device__ float g_b3 [HH];

// ---------------- prep kernels (run inside the graph, cheap) ----------------
__global__ void prep_concat(const float* __restrict__ self_w1,
                            const float* __restrict__ self_b1,
                            const float* __restrict__ inter_w1) {
    int idx = blockIdx.x * 256 + threadIdx.x;       // HH*384 = 49152
    int k = idx / 384, c = idx % 384;
    float v;
    if (c < 128)      v = self_w1[k*128 + c];
    else if (c < 256) v = inter_w1[k*128 + (c - 128)];        // wi_a rows
    else              v = inter_w1[(128 + k)*128 + (c - 256)];// wi_b rows
    g_Wc1[idx] = v;
    if (idx < 384) g_bc1[idx] = (idx < 128) ? self_b1[idx] : 0.f;
}

__global__ void prep_folds(const float* __restrict__ self_w2,
                           const float* __restrict__ inter_w2,
                           const float* __restrict__ upd_w1,
                           const float* __restrict__ upd_w2,
                           const float* __restrict__ dec_w1) {
    // grid 3*128 blocks, 128 threads; computes three 128x128 products
    int which = blockIdx.x >> 7;
    int row   = blockIdx.x & 127;
    const float *A, *Bm; float* C;
    if (which == 0)      { A = self_w2;  Bm = upd_w1;           C = g_W2a; }
    else if (which == 1) { A = inter_w2; Bm = upd_w1 + 128*128; C = g_W2b; }
    else                 { A = upd_w2;   Bm = dec_w1;           C = g_W3;  }
    __shared__ float arow[128];
    arow[threadIdx.x] = A[row*128 + threadIdx.x];
    __syncthreads();
    float acc = 0.f;
    #pragma unroll 8
    for (int k = 0; k < 128; k++) acc += arow[k] * Bm[k*128 + threadIdx.x];
    C[row*128 + threadIdx.x] = acc;
}

__global__ void prep_bias(const float* __restrict__ self_b2,
                          const float* __restrict__ inter_b2,
                          const float* __restrict__ upd_w1,
                          const float* __restrict__ upd_b1,
                          const float* __restrict__ upd_b2,
                          const float* __restrict__ dec_w1,
                          const float* __restrict__ dec_b1) {
    int n = threadIdx.x;           // 1 block, 128 threads
    float a2 = upd_b1[n], a3 = dec_b1[n];
    for (int k = 0; k < 128; k++) {
        a2 += self_b2[k]  * upd_w1[k*128 + n]
            + inter_b2[k] * upd_w1[(128 + k)*128 + n];
        a3 += upd_b2[k]   * dec_w1[k*128 + n];
    }
    g_b2[n] = a2; g_b3[n] = a3;
}

__global__ void prep_copyw(const float* __restrict__ enc_w2) {
    int i = blockIdx.x * 256 + threadIdx.x;   // 16384
    g_We2[i] = enc_w2[i];
}

__global__ void copy_x0(const float* __restrict__ gt) {
    int i = blockIdx.x * 256 + threadIdx.x;   // MR*DD = 65536
    int m = i >> 3, d = i & 7;
    int b = m >> 6, k = m & 63;
    g_x0[i] = gt[b*(TT*KS*DD) + k*DD + d];    // t = 0
}

__global__ void copy_targets(const float* __restrict__ gt, float* __restrict__ out) {
    int o = blockIdx.x * 256 + threadIdx.x;   // 327680
    int b  = o / (NST*KS*DD);
    int r  = o % (NST*KS*DD);
    int t  = r / (KS*DD);
    int kd = r % (KS*DD);
    out[MB*NST*KS*DD + o] = gt[b*(TT*KS*DD) + (t + 1)*(KS*DD) + kd];
}

// ---------------- K=8 encoder first layer (reads g_x0 directly) ----------------
__global__ void mlp_k8_relu(const float* __restrict__ W,
                            const float* __restrict__ bias) {
    int g = blockIdx.x * 256 + threadIdx.x;   // MR*HH
    int m = g >> 7, n = g & 127;
    const float* x = g_x0 + m*8;
    float acc = bias[n];
    #pragma unroll
    for (int k = 0; k < 8; k++) acc += x[k] * W[k*128 + n];
    g_He[g] = fmaxf(acc, 0.f);
}

// ---------------- main GEMM: C[64xN-tile] = act(A1@W1 [+A2@W2] + bias) ----------------
__launch_bounds__(128, 4)
__global__ void gemm64(const float* __restrict__ A1, int lda1,
                       const float* __restrict__ W1, int ldw1,
                       const float* __restrict__ A2, int lda2,
                       const float* __restrict__ W2, int ldw2,
                       const float* __restrict__ bias,
                       float* __restrict__ C, int ldc, int relu_end) {
    __shared__ float  As[32][65];      // transposed A tile (pad 65: conflict-free STS)
    __shared__ float4 Ws4[32*32];      // W tile, 32 k-rows x 128 cols as float4
    const int tid  = threadIdx.x;
    const int m0   = blockIdx.x * 64;
    const int noff = blockIdx.y * 128;
    const int rr   = tid >> 4;   // 0..7  (8 rows each)
    const int cc   = tid & 15;   // 0..15 (8 cols each)

    float acc[8][8];
    #pragma unroll
    for (int i = 0; i < 8; i++)
        #pragma unroll
        for (int j = 0; j < 8; j++) acc[i][j] = 0.f;

    const int nsrc = (A2 != nullptr) ? 2 : 1;
    for (int s = 0; s < nsrc; s++) {
        const float* Ap = s ? A2 : A1;  const int lda = s ? lda2 : lda1;
        const float* Wp = s ? W2 : W1;  const int ldw = s ? ldw2 : ldw1;
        #pragma unroll 1
        for (int kc = 0; kc < 128; kc += 32) {
            __syncthreads();
            #pragma unroll
            for (int t = 0; t < 4; t++) {               // A tile 64x32
                int l = t*128 + tid;
                int row = l >> 3, f4 = l & 7;
                float4 v = *reinterpret_cast<const float4*>(Ap + (m0+row)*lda + kc + f4*4);
                As[f4*4+0][row] = v.x; As[f4*4+1][row] = v.y;
                As[f4*4+2][row] = v.z; As[f4*4+3][row] = v.w;
            }
            #pragma unroll
            for (int t = 0; t < 8; t++) {               // W tile 32x128
                int l = t*128 + tid;
                int kr = l >> 5, fc = l & 31;
                Ws4[kr*32 + fc] = *reinterpret_cast<const float4*>(Wp + (kc+kr)*ldw + noff + fc*4);
            }
            __syncthreads();
            #pragma unroll
            for (int k = 0; k < 32; k++) {
                float4 w0 = Ws4[k*32 + cc*2];
                float4 w1 = Ws4[k*32 + cc*2 + 1];
                #pragma unroll
                for (int i = 0; i < 8; i++) {
                    float a = As[k][rr*8 + i];
                    acc[i][0] += a*w0.x; acc[i][1] += a*w0.y;
                    acc[i][2] += a*w0.z; acc[i][3] += a*w0.w;
                    acc[i][4] += a*w1.x; acc[i][5] += a*w1.y;
                    acc[i][6] += a*w1.z; acc[i][7] += a*w1.w;
                }
            }
        }
    }
    const int cbase = noff + cc*8;
    float bz[8];
    #pragma unroll
    for (int j = 0; j < 8; j++) bz[j] = bias[cbase + j];
    #pragma unroll
    for (int i = 0; i < 8; i++) {
        float o[8];
        #pragma unroll
        for (int j = 0; j < 8; j++) {
            float v = acc[i][j] + bz[j];
            if (cbase + j < relu_end) v = fmaxf(v, 0.f);
            o[j] = v;
        }
        float* cp = C + (m0 + rr*8 + i)*ldc + cbase;
        *reinterpret_cast<float4*>(cp)     = make_float4(o[0], o[1], o[2], o[3]);
        *reinterpret_cast<float4*>(cp + 4) = make_float4(o[4], o[5], o[6], o[7]);
    }
}

// ---------------- pairwise mean-relu: r[b,j,h] = mean_i relu(a[b,i,h]+bv[b,j,h]+bias[h]) ----------------
__launch_bounds__(128)
__global__ void pairwise(const float* __restrict__ ib1) {
    const int bt = blockIdx.x;     // batch
    const int jc = blockIdx.y;     // j chunk of 16
    const int h  = threadIdx.x;    // 128
    const float bias = ib1[h];
    float areg[64];
    const float* abase = g_T3 + (bt*64)*384 + 128 + h;
    #pragma unroll
    for (int i = 0; i < 64; i++) areg[i] = abase[i*384];
    const float* bbase = g_T3 + (bt*64 + jc*16)*384 + 256 + h;
    #pragma unroll 1
    for (int j = 0; j < 16; j++) {
        const float v = bbase[j*384] + bias;
        float a0 = 0.f, a1 = 0.f, a2 = 0.f, a3 = 0.f;
        #pragma unroll
        for (int i = 0; i < 64; i += 4) {
            a0 += fmaxf(areg[i+0] + v, 0.f);
            a1 += fmaxf(areg[i+1] + v, 0.f);
            a2 += fmaxf(areg[i+2] + v, 0.f);
            a3 += fmaxf(areg[i+3] + v, 0.f);
        }
        g_r[(bt*64 + jc*16 + j)*128 + h] = (a0 + a1 + a2 + a3) * (1.f/64.f);
    }
}

// ---------------- fused dec layer2 + enc layer1 ----------------
__launch_bounds__(256)
__global__ void dec_enc(const float* __restrict__ dec_w2, const float* __restrict__ dec_b2,
                        const float* __restrict__ enc_w1, const float* __restrict__ enc_b1,
                        float* __restrict__ pred_out, int step) {
    __shared__ float Hs[64][132];
    __shared__ float Wd[128*8];
    __shared__ float We[8*128];
    __shared__ float Ps[64][8];
    const int tid = threadIdx.x;
    const int m0  = blockIdx.x * 64;
    for (int l = tid; l < 64*128; l += 256) {
        int row = l >> 7, col = l & 127;
        Hs[row][col] = g_Hd[(m0+row)*128 + col];
    }
    for (int l = tid; l < 1024; l += 256) Wd[l] = dec_w2[l];
    for (int l = tid; l < 1024; l += 256) We[l] = enc_w1[l];
    __syncthreads();
    #pragma unroll
    for (int it = 0; it < 2; it++) {                 // pred = Hdec@dec_w2 + b
        int p = it*256 + tid;
        int m = p >> 3, dc = p & 7;
        float acc = dec_b2[dc];
        #pragma unroll 16
        for (int k = 0; k < 128; k++) acc += Hs[m][k] * Wd[k*8 + dc];
        Ps[m][dc] = acc;
        int mg = m0 + m;
        int bb = mg >> 6, slot = mg & 63;
        pred_out[((bb*NST + step)*KS + slot)*DD + dc] = acc;
    }
    __syncthreads();
    #pragma unroll 1
    for (int t = 0; t < 32; t++) {                   // h_enc = relu(pred@enc_w1 + b)
        int p = t*256 + tid;
        int m = p >> 7, n = p & 127;
        float acc = enc_b1[n];
        #pragma unroll
        for (int k = 0; k < 8; k++) acc += Ps[m][k] * We[k*128 + n];
        g_He[(m0+m)*128 + n] = fmaxf(acc, 0.f);
    }
}

// ---------------- launch ----------------
extern "C" void kernel_launch(void* const* d_in, const int* in_sizes, int n_in,
                              void* d_out, int out_size) {
    const float* gt       = (const float*)d_in[0];
    const float* enc_w1   = (const float*)d_in[2];
    const float* enc_b1   = (const float*)d_in[3];
    const float* enc_w2   = (const float*)d_in[4];
    const float* enc_b2   = (const float*)d_in[5];
    const float* self_w1  = (const float*)d_in[6];
    const float* self_b1  = (const float*)d_in[7];
    const float* self_w2  = (const float*)d_in[8];
    const float* self_b2  = (const float*)d_in[9];
    const float* inter_w1 = (const float*)d_in[10];
    const float* inter_b1 = (const float*)d_in[11];
    const float* inter_w2 = (const float*)d_in[12];
    const float* inter_b2 = (const float*)d_in[13];
    const float* upd_w1   = (const float*)d_in[14];
    const float* upd_b1   = (const float*)d_in[15];
    const float* upd_w2   = (const float*)d_in[16];
    const float* upd_b2   = (const float*)d_in[17];
    const float* dec_w1   = (const float*)d_in[18];
    const float* dec_b1   = (const float*)d_in[19];
    const float* dec_w2   = (const float*)d_in[20];
    const float* dec_b2   = (const float*)d_in[21];
    float* out = (float*)d_out;

    // addresses of scratch globals needed as gemm64 arguments
    float *T3, *R, *S, *Hu, *Hd, *He, *Wc1, *W2a, *W2b, *W3, *We2, *bc1, *b2, *b3;
    cudaGetSymbolAddress((void**)&T3,  g_T3);
    cudaGetSymbolAddress((void**)&R,   g_r);
    cudaGetSymbolAddress((void**)&S,   g_S);
    cudaGetSymbolAddress((void**)&Hu,  g_Hu);
    cudaGetSymbolAddress((void**)&Hd,  g_Hd);
    cudaGetSymbolAddress((void**)&He,  g_He);
    cudaGetSymbolAddress((void**)&Wc1, g_Wc1);
    cudaGetSymbolAddress((void**)&W2a, g_W2a);
    cudaGetSymbolAddress((void**)&W2b, g_W2b);
    cudaGetSymbolAddress((void**)&W3,  g_W3);
    cudaGetSymbolAddress((void**)&We2, g_We2);
    cudaGetSymbolAddress((void**)&bc1, g_bc1);
    cudaGetSymbolAddress((void**)&b2,  g_b2);
    cudaGetSymbolAddress((void**)&b3,  g_b3);

    // weight prep + input staging (cheap, part of graph)
    prep_concat<<<192, 256>>>(self_w1, self_b1, inter_w1);
    prep_folds<<<384, 128>>>(self_w2, inter_w2, upd_w1, upd_w2, dec_w1);
    prep_bias<<<1, 128>>>(self_b2, inter_b2, upd_w1, upd_b1, upd_b2, dec_w1, dec_b1);
    prep_copyw<<<64, 256>>>(enc_w2);
    copy_x0<<<256, 256>>>(gt);
    copy_targets<<<1280, 256>>>(gt, out);

    // initial encode: slots = MLP_enc(gt[:,0])
    mlp_k8_relu<<<4096, 256>>>(enc_w1, enc_b1);
    gemm64<<<dim3(128,1), 128>>>(He,128, We2,128, nullptr,0, nullptr,0, enc_b2, S,128, 0);

    for (int step = 0; step < NST; step++) {
        // [H_self | a | b] = S @ [self_w1 | wi_a | wi_b]  (relu on first 128 cols)
        gemm64<<<dim3(128,3), 128>>>(S,128, Wc1,384, nullptr,0, nullptr,0, bc1, T3,384, 128);
        // r = mean_i relu(a_i + b_j + inter_b1)
        pairwise<<<dim3(128,4), 128>>>(inter_b1);
        // Hu = relu(H_self@(self_w2@Wu1a) + r@(inter_w2@Wu1b) + b_fold)
        gemm64<<<dim3(128,1), 128>>>(T3,384, W2a,128, R,128, W2b,128, b2, Hu,128, 128);
        // Hd = relu(Hu@(upd_w2@dec_w1) + b_fold)
        gemm64<<<dim3(128,1), 128>>>(Hu,128, W3,128, nullptr,0, nullptr,0, b3, Hd,128, 128);
        // pred = Hd@dec_w2 + b  (-> output) ; He = relu(pred@enc_w1 + b)
        dec_enc<<<128, 256>>>(dec_w2, dec_b2, enc_w1, enc_b1, out, step);
        // slots = He@enc_w2 + b
        gemm64<<<dim3(128,1), 128>>>(He,128, We2,128, nullptr,0, nullptr,0, enc_b2, S,128, 0);
    }
}

// round 4
// speedup vs baseline: 1.7431x; 1.7431x over previous
#include <cuda_runtime.h>

#define MB 128        // batch
#define KS 64         // slots
#define DD 8          // state dim
#define HH 128        // slot dim
#define NST 5         // rollout steps
#define TT 6          // time steps in gt

typedef unsigned long long u64;

// ---------------- folded weights (prep kernels fill these) ----------------
__device__ float g_Wc1[HH*384];    // [self_w1 | wi_a | wi_b]
__device__ float g_W2a[HH*HH];     // self_w2 @ upd_w1[:128]
__device__ float g_W2b[HH*HH];     // inter_w2 @ upd_w1[128:]
__device__ float g_W3 [HH*HH];     // upd_w2 @ dec_w1
__device__ float g_bc1[384];       // [self_b1 | 0 | 0]
__device__ float g_b2 [HH];
__device__ float g_b3 [HH];

// ---------------- f32x2 helpers ----------------
__device__ __forceinline__ u64 pk2(float lo, float hi) {
    u64 d; asm("mov.b64 %0, {%1, %2};" : "=l"(d) : "f"(lo), "f"(hi)); return d;
}
__device__ __forceinline__ void upk2(u64 v, float& lo, float& hi) {
    asm("mov.b64 {%0, %1}, %2;" : "=f"(lo), "=f"(hi) : "l"(v));
}
__device__ __forceinline__ u64 fma2(u64 a, u64 b, u64 c) {
    u64 d; asm("fma.rn.f32x2 %0, %1, %2, %3;" : "=l"(d) : "l"(a), "l"(b), "l"(c)); return d;
}
__device__ __forceinline__ u64 add2(u64 a, u64 b) {
    u64 d; asm("add.rn.f32x2 %0, %1, %2;" : "=l"(d) : "l"(a), "l"(b)); return d;
}

// ---------------- prep kernels ----------------
__global__ void prep_concat(const float* __restrict__ self_w1,
                            const float* __restrict__ self_b1,
                            const float* __restrict__ inter_w1) {
    int idx = blockIdx.x * 256 + threadIdx.x;       // 49152
    int k = idx / 384, c = idx % 384;
    float v;
    if (c < 128)      v = self_w1[k*128 + c];
    else if (c < 256) v = inter_w1[k*128 + (c - 128)];
    else              v = inter_w1[(128 + k)*128 + (c - 256)];
    g_Wc1[idx] = v;
    if (idx < 384) g_bc1[idx] = (idx < 128) ? self_b1[idx] : 0.f;
}

__global__ void prep_folds(const float* __restrict__ self_w2,
                           const float* __restrict__ inter_w2,
                           const float* __restrict__ upd_w1,
                           const float* __restrict__ upd_w2,
                           const float* __restrict__ dec_w1) {
    int which = blockIdx.x >> 7;
    int row   = blockIdx.x & 127;
    const float *A, *Bm; float* C;
    if (which == 0)      { A = self_w2;  Bm = upd_w1;           C = g_W2a; }
    else if (which == 1) { A = inter_w2; Bm = upd_w1 + 128*128; C = g_W2b; }
    else                 { A = upd_w2;   Bm = dec_w1;           C = g_W3;  }
    __shared__ float arow[128];
    arow[threadIdx.x] = A[row*128 + threadIdx.x];
    __syncthreads();
    float acc = 0.f;
    #pragma unroll 8
    for (int k = 0; k < 128; k++) acc += arow[k] * Bm[k*128 + threadIdx.x];
    C[row*128 + threadIdx.x] = acc;
}

__global__ void prep_bias(const float* __restrict__ self_b2,
                          const float* __restrict__ inter_b2,
                          const float* __restrict__ upd_w1,
                          const float* __restrict__ upd_b1,
                          const float* __restrict__ upd_b2,
                          const float* __restrict__ dec_w1,
                          const float* __restrict__ dec_b1) {
    int n = threadIdx.x;
    float a2 = upd_b1[n], a3 = dec_b1[n];
    for (int k = 0; k < 128; k++) {
        a2 += self_b2[k]  * upd_w1[k*128 + n]
            + inter_b2[k] * upd_w1[(128 + k)*128 + n];
        a3 += upd_b2[k]   * dec_w1[k*128 + n];
    }
    g_b2[n] = a2; g_b3[n] = a3;
}

__global__ void copy_targets(const float* __restrict__ gt, float* __restrict__ out) {
    int o = blockIdx.x * 256 + threadIdx.x;   // 327680
    int b  = o / (NST*KS*DD);
    int r  = o % (NST*KS*DD);
    int t  = r / (KS*DD);
    int kd = r % (KS*DD);
    out[MB*NST*KS*DD + o] = gt[b*(TT*KS*DD) + (t + 1)*(KS*DD) + kd];
}

// ---------------- smem layout (floats) ----------------
#define OFF_S   0
#define OFF_H   8192
#define OFF_A   16384
#define OFF_B   24576
#define OFF_W   32768      /* 128x128 staged weight tile */
#define OFF_P   49152      /* 64x8 */
#define OFF_WD  49664      /* dec_w2 128x8 */
#define OFF_WE1 50688      /* enc_w1 8x128 */
#define OFF_BC1 51712
#define OFF_B2  52096
#define OFF_B3  52224
#define OFF_EB1 52352
#define OFF_EB2 52480
#define OFF_IB1 52608
#define OFF_DB2 52736
#define SM_FLOATS 52744
#define SM_BYTES  (SM_FLOATS*4)

// ---------------- block-level building blocks ----------------
__device__ __forceinline__ void stageW(float* sW, const float* __restrict__ Wg,
                                       int ldw, int col0, int tx) {
    #pragma unroll
    for (int t = 0; t < 16; t++) {
        int lin = t*256 + tx;                 // 4096 float4
        int row = lin >> 5, c4 = (lin & 31) * 4;
        *reinterpret_cast<float4*>(sW + row*128 + c4) =
            *reinterpret_cast<const float4*>(Wg + row*ldw + col0 + c4);
    }
}

__device__ __forceinline__ void ginit(u64 acc[8][4]) {
    #pragma unroll
    for (int i = 0; i < 8; i++)
        #pragma unroll
        for (int j = 0; j < 4; j++) acc[i][j] = 0ULL;
}

// acc += A(64x128 smem, row-major) @ W(128x128 smem); k-packed f32x2
__device__ __forceinline__ void gacc(u64 acc[8][4], const float* sA_, const float* sW_, int tx) {
    const int r = (tx >> 5) * 8;
    const int c = (tx & 31) * 4;
    const float* Wp = sW_ + c;
    const float* Ap = sA_ + r*128;
    #pragma unroll 2
    for (int k = 0; k < 128; k += 2) {
        float4 w0 = *reinterpret_cast<const float4*>(Wp + k*128);
        float4 w1 = *reinterpret_cast<const float4*>(Wp + (k+1)*128);
        u64 wd0 = pk2(w0.x, w1.x), wd1 = pk2(w0.y, w1.y);
        u64 wd2 = pk2(w0.z, w1.z), wd3 = pk2(w0.w, w1.w);
        #pragma unroll
        for (int i = 0; i < 8; i++) {
            u64 ap = *reinterpret_cast<const u64*>(Ap + i*128 + k);  // (A[k], A[k+1])
            acc[i][0] = fma2(ap, wd0, acc[i][0]);
            acc[i][1] = fma2(ap, wd1, acc[i][1]);
            acc[i][2] = fma2(ap, wd2, acc[i][2]);
            acc[i][3] = fma2(ap, wd3, acc[i][3]);
        }
    }
}

__device__ __forceinline__ void gepi(u64 acc[8][4], const float* sbias, bool relu,
                                     float* sC, int tx) {
    const int r = (tx >> 5) * 8;
    const int c = (tx & 31) * 4;
    float4 bz = *reinterpret_cast<const float4*>(sbias + c);
    #pragma unroll
    for (int i = 0; i < 8; i++) {
        float lo, hi; float4 o;
        upk2(acc[i][0], lo, hi); o.x = lo + hi + bz.x;
        upk2(acc[i][1], lo, hi); o.y = lo + hi + bz.y;
        upk2(acc[i][2], lo, hi); o.z = lo + hi + bz.z;
        upk2(acc[i][3], lo, hi); o.w = lo + hi + bz.w;
        if (relu) {
            o.x = fmaxf(o.x, 0.f); o.y = fmaxf(o.y, 0.f);
            o.z = fmaxf(o.z, 0.f); o.w = fmaxf(o.w, 0.f);
        }
        *reinterpret_cast<float4*>(sC + (r+i)*128 + c) = o;
    }
}

// r[j][h] = mean_i relu(a[i][h] + b[j][h] + bias[h]), via relu(x)=0.5*(x+|x|)
__device__ __forceinline__ void pairwise_fn(const float* sA_, const float* sB_,
                                            const float* sIB1, float* R, int tx) {
    const int h  = tx & 127;
    const int jh = tx >> 7;                  // 0/1 -> j halves
    const float bias = sIB1[h];
    u64 ap[32];
    float Sa = 0.f;
    #pragma unroll
    for (int i2 = 0; i2 < 32; i2++) {
        float a0 = sA_[(2*i2)*128 + h];
        float a1 = sA_[(2*i2+1)*128 + h];
        ap[i2] = pk2(a0, a1);
        Sa += a0 + a1;
    }
    const u64 MASK = 0x7FFFFFFF7FFFFFFFULL;
    const int j0 = jh * 32;
    #pragma unroll 1
    for (int j = j0; j < j0 + 32; j++) {
        float v = sB_[j*128 + h] + bias;
        u64 vv = pk2(v, v);
        u64 s2 = 0ULL;
        #pragma unroll
        for (int i2 = 0; i2 < 32; i2++) {
            u64 t = add2(ap[i2], vv);
            t &= MASK;                        // |.| on both lanes
            s2 = add2(s2, t);
        }
        float slo, shi; upk2(s2, slo, shi);
        R[j*128 + h] = ((Sa + 64.f*v) + (slo + shi)) * (0.5f / 64.f);
    }
}

// pred = Hd @ dec_w2 + db2  -> sP and global out
__device__ __forceinline__ void decf(const float* sHd, const float* sWd, const float* sDB2,
                                     float* sP, float* __restrict__ out,
                                     int b, int step, int tx) {
    const int m  = tx >> 2;
    const int d0 = (tx & 3) * 2;
    u64 acc = 0ULL;
    const float* hp = sHd + m*128;
    #pragma unroll 8
    for (int k = 0; k < 128; k++) {
        float a = hp[k];
        u64 w2 = *reinterpret_cast<const u64*>(sWd + k*8 + d0);
        acc = fma2(pk2(a, a), w2, acc);
    }
    float lo, hi; upk2(acc, lo, hi);
    lo += sDB2[d0]; hi += sDB2[d0 + 1];
    sP[m*8 + d0] = lo; sP[m*8 + d0 + 1] = hi;
    float2 pr; pr.x = lo; pr.y = hi;
    *reinterpret_cast<float2*>(out + ((b*NST + step)*KS + m)*DD + d0) = pr;
}

// sO = relu(sP(64x8) @ We1(8x128) + eb1)
__device__ __forceinline__ void enc1(const float* sPin, const float* sWe1,
                                     const float* sEB1, float* sO, int tx) {
    const int r = (tx >> 5) * 8;
    const int c = (tx & 31) * 4;
    float4 w[8];
    #pragma unroll
    for (int k = 0; k < 8; k++) w[k] = *reinterpret_cast<const float4*>(sWe1 + k*128 + c);
    float4 bz = *reinterpret_cast<const float4*>(sEB1 + c);
    #pragma unroll
    for (int i = 0; i < 8; i++) {
        float4 o = bz;
        #pragma unroll
        for (int k = 0; k < 8; k++) {
            float a = sPin[(r+i)*8 + k];
            o.x += a*w[k].x; o.y += a*w[k].y; o.z += a*w[k].z; o.w += a*w[k].w;
        }
        o.x = fmaxf(o.x, 0.f); o.y = fmaxf(o.y, 0.f);
        o.z = fmaxf(o.z, 0.f); o.w = fmaxf(o.w, 0.f);
        *reinterpret_cast<float4*>(sO + (r+i)*128 + c) = o;
    }
}

// ---------------- persistent per-batch rollout ----------------
__global__ __launch_bounds__(256, 1)
void rollout(const float* __restrict__ gt,
             const float* __restrict__ enc_w1, const float* __restrict__ enc_b1,
             const float* __restrict__ enc_w2, const float* __restrict__ enc_b2,
             const float* __restrict__ inter_b1,
             const float* __restrict__ dec_w2, const float* __restrict__ dec_b2,
             float* __restrict__ out) {
    extern __shared__ float sm[];
    float* sS  = sm + OFF_S;
    float* sH  = sm + OFF_H;
    float* sA  = sm + OFF_A;
    float* sB  = sm + OFF_B;
    float* sW  = sm + OFF_W;
    float* sP  = sm + OFF_P;
    float* sWd = sm + OFF_WD;
    float* sWe1= sm + OFF_WE1;

    const int tx = threadIdx.x;
    const int b  = blockIdx.x;

    // stage constants
    for (int i = tx; i < 1024; i += 256) { sWd[i] = dec_w2[i]; sWe1[i] = enc_w1[i]; }
    for (int i = tx; i < 384; i += 256) sm[OFF_BC1 + i] = g_bc1[i];
    if (tx < 128) {
        sm[OFF_B2  + tx] = g_b2[tx];
        sm[OFF_B3  + tx] = g_b3[tx];
        sm[OFF_EB1 + tx] = enc_b1[tx];
        sm[OFF_EB2 + tx] = enc_b2[tx];
        sm[OFF_IB1 + tx] = inter_b1[tx];
    }
    if (tx < 8) sm[OFF_DB2 + tx] = dec_b2[tx];
    // x0 = gt[b, 0]  (64x8 contiguous)
    for (int i = tx; i < 512; i += 256) sP[i] = gt[b*(TT*KS*DD) + i];
    __syncthreads();

    // initial encode: sH = relu(x0@We1+b1); sS = sH@We2 + b2
    enc1(sP, sWe1, sm + OFF_EB1, sH, tx);
    __syncthreads();
    stageW(sW, enc_w2, 128, 0, tx); __syncthreads();
    { u64 acc[8][4]; ginit(acc); gacc(acc, sH, sW, tx);
      gepi(acc, sm + OFF_EB2, false, sS, tx); }
    __syncthreads();

    #pragma unroll 1
    for (int step = 0; step < NST; step++) {
        // GEMM1: [Hself | a | b] = S @ Wc1 (relu on first slice only)
        stageW(sW, g_Wc1, 384, 0, tx); __syncthreads();
        { u64 acc[8][4]; ginit(acc); gacc(acc, sS, sW, tx);
          gepi(acc, sm + OFF_BC1, true, sH, tx); }
        __syncthreads();
        stageW(sW, g_Wc1, 384, 128, tx); __syncthreads();
        { u64 acc[8][4]; ginit(acc); gacc(acc, sS, sW, tx);
          gepi(acc, sm + OFF_BC1 + 128, false, sA, tx); }
        __syncthreads();
        stageW(sW, g_Wc1, 384, 256, tx); __syncthreads();
        { u64 acc[8][4]; ginit(acc); gacc(acc, sS, sW, tx);
          gepi(acc, sm + OFF_BC1 + 256, false, sB, tx); }
        __syncthreads();

        // pairwise -> sS (slots dead)
        pairwise_fn(sA, sB, sm + OFF_IB1, sS, tx);
        __syncthreads();

        // GEMM2 (dual): Hu = relu(Hself@W2a + r@W2b + b2) -> sA
        {
            u64 acc[8][4]; ginit(acc);
            stageW(sW, g_W2a, 128, 0, tx); __syncthreads();
            gacc(acc, sH, sW, tx); __syncthreads();
            stageW(sW, g_W2b, 128, 0, tx); __syncthreads();
            gacc(acc, sS, sW, tx);
            gepi(acc, sm + OFF_B2, true, sA, tx);
        }
        __syncthreads();

        // GEMM3: Hd = relu(Hu@W3 + b3) -> sB
        stageW(sW, g_W3, 128, 0, tx); __syncthreads();
        { u64 acc[8][4]; ginit(acc); gacc(acc, sA, sW, tx);
          gepi(acc, sm + OFF_B3, true, sB, tx); }
        __syncthreads();

        // dec: pred -> out + sP
        decf(sB, sWd, sm + OFF_DB2, sP, out, b, step, tx);
        __syncthreads();

        // re-encode: sH = relu(pred@We1+b1); sS = sH@We2 + b2
        enc1(sP, sWe1, sm + OFF_EB1, sH, tx);
        __syncthreads();
        stageW(sW, enc_w2, 128, 0, tx); __syncthreads();
        { u64 acc[8][4]; ginit(acc); gacc(acc, sH, sW, tx);
          gepi(acc, sm + OFF_EB2, false, sS, tx); }
        __syncthreads();
    }
}

// ---------------- launch ----------------
extern "C" void kernel_launch(void* const* d_in, const int* in_sizes, int n_in,
                              void* d_out, int out_size) {
    const float* gt       = (const float*)d_in[0];
    const float* enc_w1   = (const float*)d_in[2];
    const float* enc_b1   = (const float*)d_in[3];
    const float* enc_w2   = (const float*)d_in[4];
    const float* enc_b2   = (const float*)d_in[5];
    const float* self_w1  = (const float*)d_in[6];
    const float* self_b1  = (const float*)d_in[7];
    const float* self_w2  = (const float*)d_in[8];
    const float* self_b2  = (const float*)d_in[9];
    const float* inter_w1 = (const float*)d_in[10];
    const float* inter_b1 = (const float*)d_in[11];
    const float* inter_w2 = (const float*)d_in[12];
    const float* inter_b2 = (const float*)d_in[13];
    const float* upd_w1   = (const float*)d_in[14];
    const float* upd_b1   = (const float*)d_in[15];
    const float* upd_w2   = (const float*)d_in[16];
    const float* upd_b2   = (const float*)d_in[17];
    const float* dec_w1   = (const float*)d_in[18];
    const float* dec_b1   = (const float*)d_in[19];
    const float* dec_w2   = (const float*)d_in[20];
    const float* dec_b2   = (const float*)d_in[21];
    float* out = (float*)d_out;

    cudaFuncSetAttribute(rollout, cudaFuncAttributeMaxDynamicSharedMemorySize, SM_BYTES);

    copy_targets<<<1280, 256>>>(gt, out);
    prep_concat<<<192, 256>>>(self_w1, self_b1, inter_w1);
    prep_folds<<<384, 128>>>(self_w2, inter_w2, upd_w1, upd_w2, dec_w1);
    prep_bias<<<1, 128>>>(self_b2, inter_b2, upd_w1, upd_b1, upd_b2, dec_w1, dec_b1);

    rollout<<<MB, 256, SM_BYTES>>>(gt, enc_w1, enc_b1, enc_w2, enc_b2,
                                   inter_b1, dec_w2, dec_b2, out);
}

// round 5
// speedup vs baseline: 2.6735x; 1.5338x over previous
#include <cuda_runtime.h>

#define MB 128
#define KS 64
#define DD 8
#define HH 128
#define NST 5
#define TT 6

typedef unsigned long long u64;
typedef unsigned int u32;

// ---------------- folded weights ----------------
__device__ float g_Wq [HH*384];   // We2 @ [self_w1 | wi_a | wi_b]   (128 x 384)
__device__ float g_W2a[HH*HH];    // self_w2 @ upd_w1[:128]
__device__ float g_W2b[HH*HH];    // inter_w2 @ upd_w1[128:]
__device__ float g_W3 [HH*HH];    // upd_w2 @ dec_w1
__device__ float g_bq [384];      // eb2 @ Wc1 + [self_b1|0|0]
__device__ float g_b2 [HH];
__device__ float g_b3 [HH];

// ---------------- f32x2 helpers ----------------
__device__ __forceinline__ u64 pk2(float lo, float hi) {
    u64 d; asm("mov.b64 %0, {%1, %2};" : "=l"(d) : "f"(lo), "f"(hi)); return d;
}
__device__ __forceinline__ void upk2(u64 v, float& lo, float& hi) {
    asm("mov.b64 {%0, %1}, %2;" : "=f"(lo), "=f"(hi) : "l"(v));
}
__device__ __forceinline__ u64 fma2(u64 a, u64 b, u64 c) {
    u64 d; asm("fma.rn.f32x2 %0, %1, %2, %3;" : "=l"(d) : "l"(a), "l"(b), "l"(c)); return d;
}
__device__ __forceinline__ u64 add2(u64 a, u64 b) {
    u64 d; asm("add.rn.f32x2 %0, %1, %2;" : "=l"(d) : "l"(a), "l"(b)); return d;
}

// ---------------- merged prep kernel ----------------
__device__ __forceinline__ float wc1_at(int k, int c,
        const float* __restrict__ self_w1, const float* __restrict__ inter_w1) {
    if (c < 128) return self_w1[k*128 + c];
    if (c < 256) return inter_w1[k*128 + (c - 128)];
    return inter_w1[(128 + k)*128 + (c - 256)];
}

#define PB_WQ0    0
#define PB_FOLD0  128
#define PB_BQ     512
#define PB_B23    513
#define PB_TGT0   514
#define PB_TOTAL  (514 + 854)

__global__ __launch_bounds__(384)
void prep(const float* __restrict__ gt,
          const float* __restrict__ enc_w2,  const float* __restrict__ enc_b2,
          const float* __restrict__ self_w1, const float* __restrict__ self_b1,
          const float* __restrict__ self_w2, const float* __restrict__ self_b2,
          const float* __restrict__ inter_w1,
          const float* __restrict__ inter_w2, const float* __restrict__ inter_b2,
          const float* __restrict__ upd_w1,  const float* __restrict__ upd_b1,
          const float* __restrict__ upd_w2,  const float* __restrict__ upd_b2,
          const float* __restrict__ dec_w1,  const float* __restrict__ dec_b1,
          float* __restrict__ out) {
    const int bid = blockIdx.x;
    const int tx  = threadIdx.x;
    __shared__ float arow[128];

    if (bid < PB_FOLD0) {                       // Wq rows
        int row = bid;
        if (tx < 128) arow[tx] = enc_w2[row*128 + tx];
        __syncthreads();
        float acc = 0.f;
        #pragma unroll 8
        for (int k = 0; k < 128; k++) acc += arow[k] * wc1_at(k, tx, self_w1, inter_w1);
        g_Wq[row*384 + tx] = acc;
    } else if (bid < PB_BQ) {                   // W2a / W2b / W3 rows
        int which = (bid - PB_FOLD0) >> 7;
        int row   = (bid - PB_FOLD0) & 127;
        const float *A, *Bm; float* C;
        if (which == 0)      { A = self_w2;  Bm = upd_w1;           C = g_W2a; }
        else if (which == 1) { A = inter_w2; Bm = upd_w1 + 128*128; C = g_W2b; }
        else                 { A = upd_w2;   Bm = dec_w1;           C = g_W3;  }
        if (tx < 128) arow[tx] = A[row*128 + tx];
        __syncthreads();
        if (tx < 128) {
            float acc = 0.f;
            #pragma unroll 16
            for (int k = 0; k < 128; k++) acc += arow[k] * Bm[k*128 + tx];
            C[row*128 + tx] = acc;
        }
    } else if (bid == PB_BQ) {                  // bq
        if (tx < 128) arow[tx] = enc_b2[tx];
        __syncthreads();
        float acc = (tx < 128) ? self_b1[tx] : 0.f;
        #pragma unroll 16
        for (int k = 0; k < 128; k++) acc += arow[k] * wc1_at(k, tx, self_w1, inter_w1);
        g_bq[tx] = acc;
    } else if (bid == PB_B23) {                 // b2, b3
        if (tx < 128) {
            float a2 = upd_b1[tx], a3 = dec_b1[tx];
            #pragma unroll 16
            for (int k = 0; k < 128; k++) {
                a2 += self_b2[k]  * upd_w1[k*128 + tx]
                    + inter_b2[k] * upd_w1[(128 + k)*128 + tx];
                a3 += upd_b2[k]   * dec_w1[k*128 + tx];
            }
            g_b2[tx] = a2; g_b3[tx] = a3;
        }
    } else {                                    // targets copy
        int o = (bid - PB_TGT0) * 384 + tx;     // 327680 total
        if (o < MB*NST*KS*DD) {
            int b  = o / (NST*KS*DD);
            int r  = o % (NST*KS*DD);
            int t  = r / (KS*DD);
            int kd = r % (KS*DD);
            out[MB*NST*KS*DD + o] = gt[b*(TT*KS*DD) + (t + 1)*(KS*DD) + kd];
        }
    }
}

// ---------------- smem layout (floats) ----------------
#define OFF_H   0
#define OFF_A   8192
#define OFF_B   16384
#define RNG0    24576          /* 3 ring slots x 8192 floats (32KB halves) */
#define OFF_P   49152
#define OFF_WD  (OFF_P  + 512)
#define OFF_WE1 (OFF_WD + 1024)
#define OFF_BQ  (OFF_WE1+ 1024)
#define OFF_B2  (OFF_BQ + 384)
#define OFF_B3  (OFF_B2 + 128)
#define OFF_EB1 (OFF_B3 + 128)
#define OFF_IB1 (OFF_EB1+ 128)
#define OFF_DB2 (OFF_IB1+ 128)
#define SM_FLOATS (OFF_DB2 + 8)
#define SM_BYTES  (SM_FLOATS*4)

// ---------------- cp.async weight pipeline ----------------
__device__ __forceinline__ const float* half_src(int h) {
    switch (h) {
        case 0:  return g_Wq + 128;                 // 'a' cols, k 0..63
        case 1:  return g_Wq + 64*384 + 128;        // 'a' cols, k 64..127
        case 2:  return g_Wq + 256;                 // 'b'
        case 3:  return g_Wq + 64*384 + 256;
        case 4:  return g_Wq;                       // Hself
        case 5:  return g_Wq + 64*384;
        case 6:  return g_W2a;
        case 7:  return g_W2a + 64*128;
        case 8:  return g_W2b;
        case 9:  return g_W2b + 64*128;
        case 10: return g_W3;
        default: return g_W3 + 64*128;
    }
}

__device__ __forceinline__ void kick(float* slot_ptr, const float* __restrict__ src,
                                     int ldw, int tx) {
    u32 sbase = (u32)__cvta_generic_to_shared(slot_ptr);
    #pragma unroll
    for (int t = 0; t < 8; t++) {
        int lin = t*256 + tx;            // 2048 chunks of 16B (64 rows x 512B)
        int row = lin >> 5;
        int ch  = lin & 31;
        asm volatile("cp.async.cg.shared.global [%0], [%1], 16;"
                     :: "r"(sbase + (u32)((row*128 + ch*4)*4)),
                        "l"(src + row*ldw + ch*4) : "memory");
    }
    asm volatile("cp.async.commit_group;" ::: "memory");
}

// wait for current half, re-arm lookahead-2 prefetch, return smem ptr of current half
__device__ __forceinline__ const float* pipe_adv(float* ring, int& ph, int& slot, int tx) {
    asm volatile("cp.async.wait_group 1;" ::: "memory");
    __syncthreads();
    int nh = ph + 2; if (nh >= 12) nh -= 12;
    kick(ring + ((slot + 2) % 3) * 8192, half_src(nh), (nh < 6) ? 384 : 128, tx);
    const float* cur = ring + slot * 8192;
    ph = (ph + 1 == 12) ? 0 : ph + 1;
    slot = (slot + 1) % 3;
    return cur;
}

// ---------------- GEMM building blocks ----------------
__device__ __forceinline__ void ginit(u64 acc[8][4]) {
    #pragma unroll
    for (int i = 0; i < 8; i++)
        #pragma unroll
        for (int j = 0; j < 4; j++) acc[i][j] = 0ULL;
}

// acc += A(64 x 64-kslice of 128-wide rows) @ Whalf(64x128); A already offset by k0
__device__ __forceinline__ void gacc_h(u64 acc[8][4], const float* sA_,
                                       const float* sW_, int tx) {
    const int r = (tx >> 5) * 8;
    const int c = (tx & 31) * 4;
    const float* Wp = sW_ + c;
    const float* Ap = sA_ + r*128;
    #pragma unroll 2
    for (int k = 0; k < 64; k += 2) {
        float4 w0 = *reinterpret_cast<const float4*>(Wp + k*128);
        float4 w1 = *reinterpret_cast<const float4*>(Wp + (k+1)*128);
        u64 wd0 = pk2(w0.x, w1.x), wd1 = pk2(w0.y, w1.y);
        u64 wd2 = pk2(w0.z, w1.z), wd3 = pk2(w0.w, w1.w);
        #pragma unroll
        for (int i = 0; i < 8; i++) {
            u64 ap = *reinterpret_cast<const u64*>(Ap + i*128 + k);
            acc[i][0] = fma2(ap, wd0, acc[i][0]);
            acc[i][1] = fma2(ap, wd1, acc[i][1]);
            acc[i][2] = fma2(ap, wd2, acc[i][2]);
            acc[i][3] = fma2(ap, wd3, acc[i][3]);
        }
    }
}

__device__ __forceinline__ void gepi(u64 acc[8][4], const float* sbias, bool relu,
                                     float* sC, int tx) {
    const int r = (tx >> 5) * 8;
    const int c = (tx & 31) * 4;
    float4 bz = *reinterpret_cast<const float4*>(sbias + c);
    #pragma unroll
    for (int i = 0; i < 8; i++) {
        float lo, hi; float4 o;
        upk2(acc[i][0], lo, hi); o.x = lo + hi + bz.x;
        upk2(acc[i][1], lo, hi); o.y = lo + hi + bz.y;
        upk2(acc[i][2], lo, hi); o.z = lo + hi + bz.z;
        upk2(acc[i][3], lo, hi); o.w = lo + hi + bz.w;
        if (relu) {
            o.x = fmaxf(o.x, 0.f); o.y = fmaxf(o.y, 0.f);
            o.z = fmaxf(o.z, 0.f); o.w = fmaxf(o.w, 0.f);
        }
        *reinterpret_cast<float4*>(sC + (r+i)*128 + c) = o;
    }
}

// r[j][h] = mean_i relu(a[i][h]+b[j][h]+bias[h]); R may alias sA_ (regs + sync)
__device__ __forceinline__ void pairwise_fn(const float* sA_, const float* sB_,
                                            const float* sIB1, float* R, int tx) {
    const int h  = tx & 127;
    const int jh = tx >> 7;
    const float bias = sIB1[h];
    u64 ap[32];
    float Sa = 0.f;
    #pragma unroll
    for (int i2 = 0; i2 < 32; i2++) {
        float a0 = sA_[(2*i2)*128 + h];
        float a1 = sA_[(2*i2+1)*128 + h];
        ap[i2] = pk2(a0, a1);
        Sa += a0 + a1;
    }
    __syncthreads();                       // all 'a' reads done before R overwrites
    const u64 MASK = 0x7FFFFFFF7FFFFFFFULL;
    const int j0 = jh * 32;
    #pragma unroll 1
    for (int j = j0; j < j0 + 32; j++) {
        float v = sB_[j*128 + h] + bias;
        u64 vv = pk2(v, v);
        u64 s2 = 0ULL;
        #pragma unroll
        for (int i2 = 0; i2 < 32; i2++) {
            u64 t = add2(ap[i2], vv);
            t &= MASK;                     // |x| both lanes: relu(x)=0.5*(x+|x|)
            s2 = add2(s2, t);
        }
        float slo, shi; upk2(s2, slo, shi);
        R[j*128 + h] = ((Sa + 64.f*v) + (slo + shi)) * (0.5f / 64.f);
    }
}

__device__ __forceinline__ void decf(const float* sHd, const float* sWd, const float* sDB2,
                                     float* sP, float* __restrict__ out,
                                     int b, int step, int tx) {
    const int m  = tx >> 2;
    const int d0 = (tx & 3) * 2;
    u64 acc = 0ULL;
    const float* hp = sHd + m*128;
    #pragma unroll 8
    for (int k = 0; k < 128; k++) {
        float a = hp[k];
        u64 w2 = *reinterpret_cast<const u64*>(sWd + k*8 + d0);
        acc = fma2(pk2(a, a), w2, acc);
    }
    float lo, hi; upk2(acc, lo, hi);
    lo += sDB2[d0]; hi += sDB2[d0 + 1];
    sP[m*8 + d0] = lo; sP[m*8 + d0 + 1] = hi;
    float2 pr; pr.x = lo; pr.y = hi;
    *reinterpret_cast<float2*>(out + ((b*NST + step)*KS + m)*DD + d0) = pr;
}

__device__ __forceinline__ void enc1(const float* sPin, const float* sWe1,
                                     const float* sEB1, float* sO, int tx) {
    const int r = (tx >> 5) * 8;
    const int c = (tx & 31) * 4;
    float4 w[8];
    #pragma unroll
    for (int k = 0; k < 8; k++) w[k] = *reinterpret_cast<const float4*>(sWe1 + k*128 + c);
    float4 bz = *reinterpret_cast<const float4*>(sEB1 + c);
    #pragma unroll
    for (int i = 0; i < 8; i++) {
        float4 o = bz;
        #pragma unroll
        for (int k = 0; k < 8; k++) {
            float a = sPin[(r+i)*8 + k];
            o.x += a*w[k].x; o.y += a*w[k].y; o.z += a*w[k].z; o.w += a*w[k].w;
        }
        o.x = fmaxf(o.x, 0.f); o.y = fmaxf(o.y, 0.f);
        o.z = fmaxf(o.z, 0.f); o.w = fmaxf(o.w, 0.f);
        *reinterpret_cast<float4*>(sO + (r+i)*128 + c) = o;
    }
}

// ---------------- persistent per-batch rollout ----------------
__global__ __launch_bounds__(256, 1)
void rollout(const float* __restrict__ gt,
             const float* __restrict__ enc_w1, const float* __restrict__ enc_b1,
             const float* __restrict__ inter_b1,
             const float* __restrict__ dec_w2, const float* __restrict__ dec_b2,
             float* __restrict__ out) {
    extern __shared__ float sm[];
    float* sH   = sm + OFF_H;
    float* sA   = sm + OFF_A;
    float* sB   = sm + OFF_B;
    float* ring = sm + RNG0;
    float* sP   = sm + OFF_P;
    float* sWd  = sm + OFF_WD;
    float* sWe1 = sm + OFF_WE1;

    const int tx = threadIdx.x;
    const int b  = blockIdx.x;

    for (int i = tx; i < 1024; i += 256) { sWd[i] = dec_w2[i]; sWe1[i] = enc_w1[i]; }
    for (int i = tx; i < 384; i += 256) sm[OFF_BQ + i] = g_bq[i];
    if (tx < 128) {
        sm[OFF_B2  + tx] = g_b2[tx];
        sm[OFF_B3  + tx] = g_b3[tx];
        sm[OFF_EB1 + tx] = enc_b1[tx];
        sm[OFF_IB1 + tx] = inter_b1[tx];
    }
    if (tx < 8) sm[OFF_DB2 + tx] = dec_b2[tx];
    for (int i = tx; i < 512; i += 256) sP[i] = gt[b*(TT*KS*DD) + i];  // x0
    __syncthreads();

    enc1(sP, sWe1, sm + OFF_EB1, sH, tx);    // He0
    __syncthreads();

    int ph = 0, slot = 0;
    kick(ring,        half_src(0), 384, tx);
    kick(ring + 8192, half_src(1), 384, tx);

    #pragma unroll 1
    for (int step = 0; step < NST; step++) {
        u64 acc[8][4];
        const float* w;
        // a = He @ Wq[:,128:256] + bq[128:256]      -> sA
        ginit(acc);
        w = pipe_adv(ring, ph, slot, tx); gacc_h(acc, sH,      w, tx);
        w = pipe_adv(ring, ph, slot, tx); gacc_h(acc, sH + 64, w, tx);
        gepi(acc, sm + OFF_BQ + 128, false, sA, tx);
        // b = He @ Wq[:,256:384] + bq[256:384]      -> sB
        ginit(acc);
        w = pipe_adv(ring, ph, slot, tx); gacc_h(acc, sH,      w, tx);
        w = pipe_adv(ring, ph, slot, tx); gacc_h(acc, sH + 64, w, tx);
        gepi(acc, sm + OFF_BQ + 256, false, sB, tx);
        __syncthreads();
        // r -> sA (in place, regs+sync inside)
        pairwise_fn(sA, sB, sm + OFF_IB1, sA, tx);
        // Hself = relu(He @ Wq[:,0:128] + bq[0:128]) -> sB
        ginit(acc);
        w = pipe_adv(ring, ph, slot, tx); gacc_h(acc, sH,      w, tx);
        w = pipe_adv(ring, ph, slot, tx); gacc_h(acc, sH + 64, w, tx);
        gepi(acc, sm + OFF_BQ, true, sB, tx);
        // Hu = relu(Hself@W2a + r@W2b + b2)          -> sH
        ginit(acc);
        w = pipe_adv(ring, ph, slot, tx); gacc_h(acc, sB,      w, tx);
        w = pipe_adv(ring, ph, slot, tx); gacc_h(acc, sB + 64, w, tx);
        w = pipe_adv(ring, ph, slot, tx); gacc_h(acc, sA,      w, tx);
        w = pipe_adv(ring, ph, slot, tx); gacc_h(acc, sA + 64, w, tx);
        gepi(acc, sm + OFF_B2, true, sH, tx);
        // Hd = relu(Hu@W3 + b3)                      -> sA
        ginit(acc);
        w = pipe_adv(ring, ph, slot, tx); gacc_h(acc, sH,      w, tx);
        w = pipe_adv(ring, ph, slot, tx); gacc_h(acc, sH + 64, w, tx);
        gepi(acc, sm + OFF_B3, true, sA, tx);
        __syncthreads();
        // pred -> out + sP
        decf(sA, sWd, sm + OFF_DB2, sP, out, b, step, tx);
        __syncthreads();
        // He' = relu(pred@We1 + eb1) -> sH
        enc1(sP, sWe1, sm + OFF_EB1, sH, tx);
    }
}

// ---------------- launch ----------------
extern "C" void kernel_launch(void* const* d_in, const int* in_sizes, int n_in,
                              void* d_out, int out_size) {
    const float* gt       = (const float*)d_in[0];
    const float* enc_w1   = (const float*)d_in[2];
    const float* enc_b1   = (const float*)d_in[3];
    const float* enc_w2   = (const float*)d_in[4];
    const float* enc_b2   = (const float*)d_in[5];
    const float* self_w1  = (const float*)d_in[6];
    const float* self_b1  = (const float*)d_in[7];
    const float* self_w2  = (const float*)d_in[8];
    const float* self_b2  = (const float*)d_in[9];
    const float* inter_w1 = (const float*)d_in[10];
    const float* inter_b1 = (const float*)d_in[11];
    const float* inter_w2 = (const float*)d_in[12];
    const float* inter_b2 = (const float*)d_in[13];
    const float* upd_w1   = (const float*)d_in[14];
    const float* upd_b1   = (const float*)d_in[15];
    const float* upd_w2   = (const float*)d_in[16];
    const float* upd_b2   = (const float*)d_in[17];
    const float* dec_w1   = (const float*)d_in[18];
    const float* dec_b1   = (const float*)d_in[19];
    const float* dec_w2   = (const float*)d_in[20];
    const float* dec_b2   = (const float*)d_in[21];
    float* out = (float*)d_out;

    cudaFuncSetAttribute(rollout, cudaFuncAttributeMaxDynamicSharedMemorySize, SM_BYTES);

    prep<<<PB_TOTAL, 384>>>(gt, enc_w2, enc_b2, self_w1, self_b1, self_w2, self_b2,
                            inter_w1, inter_w2, inter_b2, upd_w1, upd_b1,
                            upd_w2, upd_b2, dec_w1, dec_b1, out);

    rollout<<<MB, 256, SM_BYTES>>>(gt, enc_w1, enc_b1, inter_b1, dec_w2, dec_b2, out);
}

// round 6
// speedup vs baseline: 3.1652x; 1.1839x over previous
#include <cuda_runtime.h>

#define MB 128
#define KS 64
#define DD 8
#define HH 128
#define NST 5
#define TT 6

typedef unsigned long long u64;
typedef unsigned int u32;

// ---------------- folded weights ----------------
// g_Wpk: 12 halves of 64x128, k-pair packed: [half][(k&63)/2 * 256 + col*2 + (k&1)]
// half order: 0,1: Wq 'a' cols (k0,k1) | 2,3: Wq 'b' | 4,5: Wq 'self' | 6,7: W2a | 8,9: W2b | 10,11: W3
__device__ float g_Wpk[12*8192];
__device__ float g_bq [384];      // eb2 @ [self_w1|wi_a|wi_b] + [self_b1|0|0]
__device__ float g_b2 [HH];
__device__ float g_b3 [HH];

// ---------------- f32x2 helpers ----------------
__device__ __forceinline__ u64 pk2(float lo, float hi) {
    u64 d; asm("mov.b64 %0, {%1, %2};" : "=l"(d) : "f"(lo), "f"(hi)); return d;
}
__device__ __forceinline__ void upk2(u64 v, float& lo, float& hi) {
    asm("mov.b64 {%0, %1}, %2;" : "=f"(lo), "=f"(hi) : "l"(v));
}
__device__ __forceinline__ u64 fma2(u64 a, u64 b, u64 c) {
    u64 d; asm("fma.rn.f32x2 %0, %1, %2, %3;" : "=l"(d) : "l"(a), "l"(b), "l"(c)); return d;
}
__device__ __forceinline__ u64 add2(u64 a, u64 b) {
    u64 d; asm("add.rn.f32x2 %0, %1, %2;" : "=l"(d) : "l"(a), "l"(b)); return d;
}

// ---------------- merged prep kernel ----------------
__device__ __forceinline__ float wc1_at(int k, int c,
        const float* __restrict__ self_w1, const float* __restrict__ inter_w1) {
    if (c < 128) return self_w1[k*128 + c];
    if (c < 256) return inter_w1[k*128 + (c - 128)];
    return inter_w1[(128 + k)*128 + (c - 256)];
}

#define PB_FOLD0  128
#define PB_BQ     512
#define PB_B23    513
#define PB_TGT0   514
#define PB_TOTAL  (514 + 854)

__global__ __launch_bounds__(384)
void prep(const float* __restrict__ gt,
          const float* __restrict__ enc_w2,  const float* __restrict__ enc_b2,
          const float* __restrict__ self_w1, const float* __restrict__ self_b1,
          const float* __restrict__ self_w2, const float* __restrict__ self_b2,
          const float* __restrict__ inter_w1,
          const float* __restrict__ inter_w2, const float* __restrict__ inter_b2,
          const float* __restrict__ upd_w1,  const float* __restrict__ upd_b1,
          const float* __restrict__ upd_w2,  const float* __restrict__ upd_b2,
          const float* __restrict__ dec_w1,  const float* __restrict__ dec_b1,
          float* __restrict__ out) {
    const int bid = blockIdx.x;
    const int tx  = threadIdx.x;
    __shared__ float arow[128];

    if (bid < PB_FOLD0) {                       // Wq rows: row k = bid, col c = tx (0..383)
        int k = bid;
        if (tx < 128) arow[tx] = enc_w2[k*128 + tx];
        __syncthreads();
        float acc = 0.f;
        #pragma unroll 8
        for (int kk = 0; kk < 128; kk++) acc += arow[kk] * wc1_at(kk, tx, self_w1, inter_w1);
        int slice = tx >> 7;                    // 0:self 1:a 2:b
        int base  = (slice == 0) ? 4 : (slice == 1) ? 0 : 2;
        int half  = base + (k >> 6);
        int kk6   = k & 63;
        g_Wpk[half*8192 + (kk6 >> 1)*256 + (tx & 127)*2 + (kk6 & 1)] = acc;
    } else if (bid < PB_BQ) {                   // W2a / W2b / W3 rows
        int which = (bid - PB_FOLD0) >> 7;
        int k     = (bid - PB_FOLD0) & 127;
        const float *A, *Bm;
        if (which == 0)      { A = self_w2;  Bm = upd_w1; }
        else if (which == 1) { A = inter_w2; Bm = upd_w1 + 128*128; }
        else                 { A = upd_w2;   Bm = dec_w1; }
        if (tx < 128) arow[tx] = A[k*128 + tx];
        __syncthreads();
        if (tx < 128) {
            float acc = 0.f;
            #pragma unroll 16
            for (int kk = 0; kk < 128; kk++) acc += arow[kk] * Bm[kk*128 + tx];
            int half = 6 + 2*which + (k >> 6);
            int kk6  = k & 63;
            g_Wpk[half*8192 + (kk6 >> 1)*256 + tx*2 + (kk6 & 1)] = acc;
        }
    } else if (bid == PB_BQ) {                  // bq
        if (tx < 128) arow[tx] = enc_b2[tx];
        __syncthreads();
        float acc = (tx < 128) ? self_b1[tx] : 0.f;
        #pragma unroll 16
        for (int kk = 0; kk < 128; kk++) acc += arow[kk] * wc1_at(kk, tx, self_w1, inter_w1);
        g_bq[tx] = acc;
    } else if (bid == PB_B23) {                 // b2, b3
        if (tx < 128) {
            float a2 = upd_b1[tx], a3 = dec_b1[tx];
            #pragma unroll 16
            for (int kk = 0; kk < 128; kk++) {
                a2 += self_b2[kk]  * upd_w1[kk*128 + tx]
                    + inter_b2[kk] * upd_w1[(128 + kk)*128 + tx];
                a3 += upd_b2[kk]   * dec_w1[kk*128 + tx];
            }
            g_b2[tx] = a2; g_b3[tx] = a3;
        }
    } else {                                    // targets copy
        int o = (bid - PB_TGT0) * 384 + tx;
        if (o < MB*NST*KS*DD) {
            int b  = o / (NST*KS*DD);
            int r  = o % (NST*KS*DD);
            int t  = r / (KS*DD);
            int kd = r % (KS*DD);
            out[MB*NST*KS*DD + o] = gt[b*(TT*KS*DD) + (t + 1)*(KS*DD) + kd];
        }
    }
}

// ---------------- smem layout (floats) ----------------
#define OFF_H   0
#define OFF_A   8192
#define OFF_B   16384
#define RNG0    24576          /* 3 ring slots x 8192 floats */
#define OFF_P   49152
#define OFF_WDP (OFF_P  + 512)
#define OFF_WE1 (OFF_WDP+ 1024)
#define OFF_BQ  (OFF_WE1+ 1024)
#define OFF_B2  (OFF_BQ + 384)
#define OFF_B3  (OFF_B2 + 128)
#define OFF_EB1 (OFF_B3 + 128)
#define OFF_IB1 (OFF_EB1+ 128)
#define OFF_DB2 (OFF_IB1+ 128)
#define SM_FLOATS (OFF_DB2 + 8)
#define SM_BYTES  (SM_FLOATS*4)

// ---------------- cp.async weight pipeline (packed, contiguous 32KB halves) ----------------
__device__ __forceinline__ void kick(float* slot_ptr, const float* __restrict__ src, int tx) {
    u32 sbase = (u32)__cvta_generic_to_shared(slot_ptr);
    #pragma unroll
    for (int t = 0; t < 4; t++) {
        int lin = t*512 + tx;            // 2048 chunks of 16B
        asm volatile("cp.async.cg.shared.global [%0], [%1], 16;"
                     :: "r"(sbase + (u32)(lin*16)), "l"(src + lin*4) : "memory");
    }
    asm volatile("cp.async.commit_group;" ::: "memory");
}

__device__ __forceinline__ const float* pipe_adv(float* ring, int& ph, int& slot, int tx) {
    asm volatile("cp.async.wait_group 1;" ::: "memory");
    __syncthreads();
    int nh = ph + 2; if (nh >= 12) nh -= 12;
    kick(ring + ((slot + 2) % 3) * 8192, g_Wpk + nh*8192, tx);
    const float* cur = ring + slot * 8192;
    ph = (ph + 1 == 12) ? 0 : ph + 1;
    slot = (slot + 1) % 3;
    return cur;
}

// ---------------- GEMM building blocks (512 threads: 8 rows x 2 cols each) ----------------
__device__ __forceinline__ void ginit(u64 acc[8][2]) {
    #pragma unroll
    for (int i = 0; i < 8; i++) { acc[i][0] = 0ULL; acc[i][1] = 0ULL; }
}

// acc += A(64 rows x 64-k slice) @ Wpacked(64x128); sA_ pre-offset by k0
__device__ __forceinline__ void gacc_h(u64 acc[8][2], const float* sA_,
                                       const float* sW_, int tx) {
    const int rg = tx >> 6;          // 0..7
    const int cg = tx & 63;          // 0..63
    const float* Wp = sW_ + cg*4;
    const float* Ap = sA_ + rg*8*128;
    #pragma unroll 4
    for (int k4 = 0; k4 < 16; k4++) {
        ulonglong2 wv0 = *reinterpret_cast<const ulonglong2*>(Wp + (2*k4)*256);
        ulonglong2 wv1 = *reinterpret_cast<const ulonglong2*>(Wp + (2*k4+1)*256);
        #pragma unroll
        for (int i = 0; i < 8; i++) {
            ulonglong2 av = *reinterpret_cast<const ulonglong2*>(Ap + i*128 + k4*4);
            acc[i][0] = fma2(av.x, wv0.x, acc[i][0]);
            acc[i][1] = fma2(av.x, wv0.y, acc[i][1]);
            acc[i][0] = fma2(av.y, wv1.x, acc[i][0]);
            acc[i][1] = fma2(av.y, wv1.y, acc[i][1]);
        }
    }
}

__device__ __forceinline__ void gepi(u64 acc[8][2], const float* sbias, bool relu,
                                     float* sC, int tx) {
    const int rg = tx >> 6, cg = tx & 63;
    float2 bz = *reinterpret_cast<const float2*>(sbias + cg*2);
    #pragma unroll
    for (int i = 0; i < 8; i++) {
        float lo, hi; float2 o;
        upk2(acc[i][0], lo, hi); o.x = lo + hi + bz.x;
        upk2(acc[i][1], lo, hi); o.y = lo + hi + bz.y;
        if (relu) { o.x = fmaxf(o.x, 0.f); o.y = fmaxf(o.y, 0.f); }
        *reinterpret_cast<float2*>(sC + (rg*8 + i)*128 + cg*2) = o;
    }
}

// r[j][h] = mean_i relu(a[i][h]+b[j][h]+bias[h]); R may alias sA_ (regs + sync)
__device__ __forceinline__ void pairwise_fn(const float* sA_, const float* sB_,
                                            const float* sIB1, float* R, int tx) {
    const int h  = tx & 127;
    const int jq = tx >> 7;                // 0..3 -> 16 j each
    const float bias = sIB1[h];
    u64 ap[32];
    float Sa = 0.f;
    #pragma unroll
    for (int i2 = 0; i2 < 32; i2++) {
        float a0 = sA_[(2*i2)*128 + h];
        float a1 = sA_[(2*i2+1)*128 + h];
        ap[i2] = pk2(a0, a1);
        Sa += a0 + a1;
    }
    __syncthreads();                       // all 'a' reads done before R overwrites
    const u64 MASK = 0x7FFFFFFF7FFFFFFFULL;
    const int j0 = jq * 16;
    #pragma unroll 1
    for (int j = j0; j < j0 + 16; j++) {
        float v = sB_[j*128 + h] + bias;
        u64 vv = pk2(v, v);
        u64 s2 = 0ULL;
        #pragma unroll
        for (int i2 = 0; i2 < 32; i2++) {
            u64 t = add2(ap[i2], vv);
            t &= MASK;                     // |x| both lanes: relu(x)=0.5*(x+|x|)
            s2 = add2(s2, t);
        }
        float slo, shi; upk2(s2, slo, shi);
        R[j*128 + h] = ((Sa + 64.f*v) + (slo + shi)) * (0.5f / 64.f);
    }
}

// pred = Hd @ dec_w2 + db2 -> sP and global out (one output per thread)
__device__ __forceinline__ void decf(const float* sHd, const float* sWdp, const float* sDB2,
                                     float* sP, float* __restrict__ out,
                                     int b, int step, int tx) {
    const int m = tx >> 3;
    const int d = tx & 7;
    u64 acc = 0ULL;
    const float* hp = sHd + m*128;
    const float* wp = sWdp + d*2;
    #pragma unroll 8
    for (int k2 = 0; k2 < 64; k2++)
        acc = fma2(*reinterpret_cast<const u64*>(hp + 2*k2),
                   *reinterpret_cast<const u64*>(wp + k2*16), acc);
    float lo, hi; upk2(acc, lo, hi);
    float val = lo + hi + sDB2[d];
    sP[m*8 + d] = val;
    out[((b*NST + step)*KS + m)*DD + d] = val;
}

// sO = relu(sP(64x8) @ We1(8x128) + eb1); 8 rows x 2 cols per thread
__device__ __forceinline__ void enc1(const float* sPin, const float* sWe1,
                                     const float* sEB1, float* sO, int tx) {
    const int r0 = (tx >> 6) * 8;
    const int c0 = (tx & 63) * 2;
    float2 w[8];
    #pragma unroll
    for (int k = 0; k < 8; k++) w[k] = *reinterpret_cast<const float2*>(sWe1 + k*128 + c0);
    float2 bz = *reinterpret_cast<const float2*>(sEB1 + c0);
    #pragma unroll
    for (int i = 0; i < 8; i++) {
        float2 o = bz;
        #pragma unroll
        for (int k = 0; k < 8; k++) {
            float a = sPin[(r0+i)*8 + k];
            o.x += a*w[k].x; o.y += a*w[k].y;
        }
        o.x = fmaxf(o.x, 0.f); o.y = fmaxf(o.y, 0.f);
        *reinterpret_cast<float2*>(sO + (r0+i)*128 + c0) = o;
    }
}

// ---------------- persistent per-batch rollout ----------------
__global__ __launch_bounds__(512, 1)
void rollout(const float* __restrict__ gt,
             const float* __restrict__ enc_w1, const float* __restrict__ enc_b1,
             const float* __restrict__ inter_b1,
             const float* __restrict__ dec_w2, const float* __restrict__ dec_b2,
             float* __restrict__ out) {
    extern __shared__ float sm[];
    float* sH   = sm + OFF_H;
    float* sA   = sm + OFF_A;
    float* sB   = sm + OFF_B;
    float* ring = sm + RNG0;
    float* sP   = sm + OFF_P;
    float* sWdp = sm + OFF_WDP;
    float* sWe1 = sm + OFF_WE1;

    const int tx = threadIdx.x;
    const int b  = blockIdx.x;

    #pragma unroll
    for (int t = 0; t < 2; t++) {
        int i = t*512 + tx;
        sWe1[i] = enc_w1[i];
        int k = i >> 3, d = i & 7;                       // pack dec_w2 in k-pairs
        sWdp[(k >> 1)*16 + d*2 + (k & 1)] = dec_w2[i];
    }
    if (tx < 384) sm[OFF_BQ + tx] = g_bq[tx];
    if (tx < 128) {
        sm[OFF_B2  + tx] = g_b2[tx];
        sm[OFF_B3  + tx] = g_b3[tx];
        sm[OFF_EB1 + tx] = enc_b1[tx];
        sm[OFF_IB1 + tx] = inter_b1[tx];
    }
    if (tx < 8) sm[OFF_DB2 + tx] = dec_b2[tx];
    sP[tx] = gt[b*(TT*KS*DD) + tx];                      // x0 (512 floats)
    __syncthreads();

    enc1(sP, sWe1, sm + OFF_EB1, sH, tx);                // He0

    int ph = 0, slot = 0;
    kick(ring,        g_Wpk,        tx);
    kick(ring + 8192, g_Wpk + 8192, tx);

    #pragma unroll 1
    for (int step = 0; step < NST; step++) {
        u64 acc[8][2];
        const float* w;
        // a = He @ Wq_a + bq[128:256] -> sA
        ginit(acc);
        w = pipe_adv(ring, ph, slot, tx); gacc_h(acc, sH,      w, tx);
        w = pipe_adv(ring, ph, slot, tx); gacc_h(acc, sH + 64, w, tx);
        gepi(acc, sm + OFF_BQ + 128, false, sA, tx);
        // b = He @ Wq_b + bq[256:384] -> sB
        ginit(acc);
        w = pipe_adv(ring, ph, slot, tx); gacc_h(acc, sH,      w, tx);
        w = pipe_adv(ring, ph, slot, tx); gacc_h(acc, sH + 64, w, tx);
        gepi(acc, sm + OFF_BQ + 256, false, sB, tx);
        __syncthreads();
        // r -> sA (in place; internal reg-load + sync)
        pairwise_fn(sA, sB, sm + OFF_IB1, sA, tx);
        // Hself = relu(He @ Wq_self + bq[0:128]) -> sB
        ginit(acc);
        w = pipe_adv(ring, ph, slot, tx); gacc_h(acc, sH,      w, tx);
        w = pipe_adv(ring, ph, slot, tx); gacc_h(acc, sH + 64, w, tx);
        gepi(acc, sm + OFF_BQ, true, sB, tx);
        // Hu = relu(Hself@W2a + r@W2b + b2) -> sH
        ginit(acc);
        w = pipe_adv(ring, ph, slot, tx); gacc_h(acc, sB,      w, tx);
        w = pipe_adv(ring, ph, slot, tx); gacc_h(acc, sB + 64, w, tx);
        w = pipe_adv(ring, ph, slot, tx); gacc_h(acc, sA,      w, tx);
        w = pipe_adv(ring, ph, slot, tx); gacc_h(acc, sA + 64, w, tx);
        gepi(acc, sm + OFF_B2, true, sH, tx);
        // Hd = relu(Hu@W3 + b3) -> sA
        ginit(acc);
        w = pipe_adv(ring, ph, slot, tx); gacc_h(acc, sH,      w, tx);
        w = pipe_adv(ring, ph, slot, tx); gacc_h(acc, sH + 64, w, tx);
        gepi(acc, sm + OFF_B3, true, sA, tx);
        __syncthreads();
        // pred -> out + sP
        decf(sA, sWdp, sm + OFF_DB2, sP, out, b, step, tx);
        if (step + 1 < NST) {
            __syncthreads();
            enc1(sP, sWe1, sm + OFF_EB1, sH, tx);        // He'
        }
    }
}

// ---------------- launch ----------------
extern "C" void kernel_launch(void* const* d_in, const int* in_sizes, int n_in,
                              void* d_out, int out_size) {
    const float* gt       = (const float*)d_in[0];
    const float* enc_w1   = (const float*)d_in[2];
    const float* enc_b1   = (const float*)d_in[3];
    const float* enc_w2   = (const float*)d_in[4];
    const float* enc_b2   = (const float*)d_in[5];
    const float* self_w1  = (const float*)d_in[6];
    const float* self_b1  = (const float*)d_in[7];
    const float* self_w2  = (const float*)d_in[8];
    const float* self_b2  = (const float*)d_in[9];
    const float* inter_w1 = (const float*)d_in[10];
    const float* inter_b1 = (const float*)d_in[11];
    const float* inter_w2 = (const float*)d_in[12];
    const float* inter_b2 = (const float*)d_in[13];
    const float* upd_w1   = (const float*)d_in[14];
    const float* upd_b1   = (const float*)d_in[15];
    const float* upd_w2   = (const float*)d_in[16];
    const float* upd_b2   = (const float*)d_in[17];
    const float* dec_w1   = (const float*)d_in[18];
    const float* dec_b1   = (const float*)d_in[19];
    const float* dec_w2   = (const float*)d_in[20];
    const float* dec_b2   = (const float*)d_in[21];
    float* out = (float*)d_out;

    cudaFuncSetAttribute(rollout, cudaFuncAttributeMaxDynamicSharedMemorySize, SM_BYTES);

    prep<<<PB_TOTAL, 384>>>(gt, enc_w2, enc_b2, self_w1, self_b1, self_w2, self_b2,
                            inter_w1, inter_w2, inter_b2, upd_w1, upd_b1,
                            upd_w2, upd_b2, dec_w1, dec_b1, out);

    rollout<<<MB, 512, SM_BYTES>>>(gt, enc_w1, enc_b1, inter_b1, dec_w2, dec_b2, out);
}

// round 7
// speedup vs baseline: 3.1825x; 1.0055x over previous
#include <cuda_runtime.h>

#define MB 128
#define KS 64
#define DD 8
#define HH 128
#define NST 5
#define TT 6

typedef unsigned long long u64;
typedef unsigned int u32;

// ---------------- folded weights ----------------
// g_Wpk: 12 halves of 64x128, k-pair packed: [half][(k&63)/2 * 256 + col*2 + (k&1)]
// half order: 0,1: Wq 'a' | 2,3: Wq 'b' | 4,5: Wq 'self' | 6,7: W2a | 8,9: W2b | 10,11: W3
__device__ float g_Wpk[12*8192];
__device__ float g_bq [384];
__device__ float g_b2 [HH];
__device__ float g_b3 [HH];

// ---------------- f32x2 helpers ----------------
__device__ __forceinline__ u64 pk2(float lo, float hi) {
    u64 d; asm("mov.b64 %0, {%1, %2};" : "=l"(d) : "f"(lo), "f"(hi)); return d;
}
__device__ __forceinline__ void upk2(u64 v, float& lo, float& hi) {
    asm("mov.b64 {%0, %1}, %2;" : "=f"(lo), "=f"(hi) : "l"(v));
}
__device__ __forceinline__ u64 fma2(u64 a, u64 b, u64 c) {
    u64 d; asm("fma.rn.f32x2 %0, %1, %2, %3;" : "=l"(d) : "l"(a), "l"(b), "l"(c)); return d;
}
__device__ __forceinline__ u64 add2(u64 a, u64 b) {
    u64 d; asm("add.rn.f32x2 %0, %1, %2;" : "=l"(d) : "l"(a), "l"(b)); return d;
}

// ---------------- merged prep kernel ----------------
__device__ __forceinline__ float wc1_at(int k, int c,
        const float* __restrict__ self_w1, const float* __restrict__ inter_w1) {
    if (c < 128) return self_w1[k*128 + c];
    if (c < 256) return inter_w1[k*128 + (c - 128)];
    return inter_w1[(128 + k)*128 + (c - 256)];
}

#define PB_FOLD0  128
#define PB_BQ     512
#define PB_B23    513
#define PB_TGT0   514
#define PB_TOTAL  (514 + 854)

__global__ __launch_bounds__(384)
void prep(const float* __restrict__ gt,
          const float* __restrict__ enc_w2,  const float* __restrict__ enc_b2,
          const float* __restrict__ self_w1, const float* __restrict__ self_b1,
          const float* __restrict__ self_w2, const float* __restrict__ self_b2,
          const float* __restrict__ inter_w1,
          const float* __restrict__ inter_w2, const float* __restrict__ inter_b2,
          const float* __restrict__ upd_w1,  const float* __restrict__ upd_b1,
          const float* __restrict__ upd_w2,  const float* __restrict__ upd_b2,
          const float* __restrict__ dec_w1,  const float* __restrict__ dec_b1,
          float* __restrict__ out) {
    const int bid = blockIdx.x;
    const int tx  = threadIdx.x;
    __shared__ float arow[128];

    if (bid < PB_FOLD0) {                       // Wq rows
        int k = bid;
        if (tx < 128) arow[tx] = enc_w2[k*128 + tx];
        __syncthreads();
        float acc = 0.f;
        #pragma unroll 8
        for (int kk = 0; kk < 128; kk++) acc += arow[kk] * wc1_at(kk, tx, self_w1, inter_w1);
        int slice = tx >> 7;                    // 0:self 1:a 2:b
        int base  = (slice == 0) ? 4 : (slice == 1) ? 0 : 2;
        int half  = base + (k >> 6);
        int kk6   = k & 63;
        g_Wpk[half*8192 + (kk6 >> 1)*256 + (tx & 127)*2 + (kk6 & 1)] = acc;
    } else if (bid < PB_BQ) {                   // W2a / W2b / W3 rows
        int which = (bid - PB_FOLD0) >> 7;
        int k     = (bid - PB_FOLD0) & 127;
        const float *A, *Bm;
        if (which == 0)      { A = self_w2;  Bm = upd_w1; }
        else if (which == 1) { A = inter_w2; Bm = upd_w1 + 128*128; }
        else                 { A = upd_w2;   Bm = dec_w1; }
        if (tx < 128) arow[tx] = A[k*128 + tx];
        __syncthreads();
        if (tx < 128) {
            float acc = 0.f;
            #pragma unroll 16
            for (int kk = 0; kk < 128; kk++) acc += arow[kk] * Bm[kk*128 + tx];
            int half = 6 + 2*which + (k >> 6);
            int kk6  = k & 63;
            g_Wpk[half*8192 + (kk6 >> 1)*256 + tx*2 + (kk6 & 1)] = acc;
        }
    } else if (bid == PB_BQ) {                  // bq
        if (tx < 128) arow[tx] = enc_b2[tx];
        __syncthreads();
        float acc = (tx < 128) ? self_b1[tx] : 0.f;
        #pragma unroll 16
        for (int kk = 0; kk < 128; kk++) acc += arow[kk] * wc1_at(kk, tx, self_w1, inter_w1);
        g_bq[tx] = acc;
    } else if (bid == PB_B23) {                 // b2, b3
        if (tx < 128) {
            float a2 = upd_b1[tx], a3 = dec_b1[tx];
            #pragma unroll 16
            for (int kk = 0; kk < 128; kk++) {
                a2 += self_b2[kk]  * upd_w1[kk*128 + tx]
                    + inter_b2[kk] * upd_w1[(128 + kk)*128 + tx];
                a3 += upd_b2[kk]   * dec_w1[kk*128 + tx];
            }
            g_b2[tx] = a2; g_b3[tx] = a3;
        }
    } else {                                    // targets copy
        int o = (bid - PB_TGT0) * 384 + tx;
        if (o < MB*NST*KS*DD) {
            int b  = o / (NST*KS*DD);
            int r  = o % (NST*KS*DD);
            int t  = r / (KS*DD);
            int kd = r % (KS*DD);
            out[MB*NST*KS*DD + o] = gt[b*(TT*KS*DD) + (t + 1)*(KS*DD) + kd];
        }
    }
}

// ---------------- smem layout (floats) ----------------
#define OFF_H   0
#define OFF_A   8192
#define OFF_B   16384
#define RNG0    24576
#define OFF_P   49152
#define OFF_WDP (OFF_P  + 512)
#define OFF_WE1 (OFF_WDP+ 1024)
#define OFF_BQ  (OFF_WE1+ 1024)
#define OFF_B2  (OFF_BQ + 384)
#define OFF_B3  (OFF_B2 + 128)
#define OFF_EB1 (OFF_B3 + 128)
#define OFF_IB1 (OFF_EB1+ 128)
#define OFF_DB2 (OFF_IB1+ 128)
#define SM_FLOATS (OFF_DB2 + 8)
#define SM_BYTES  (SM_FLOATS*4)

// ---------------- cp.async weight pipeline ----------------
__device__ __forceinline__ void kick(float* slot_ptr, const float* __restrict__ src, int tx) {
    u32 sbase = (u32)__cvta_generic_to_shared(slot_ptr);
    #pragma unroll
    for (int t = 0; t < 4; t++) {
        int lin = t*512 + tx;
        asm volatile("cp.async.cg.shared.global [%0], [%1], 16;"
                     :: "r"(sbase + (u32)(lin*16)), "l"(src + lin*4) : "memory");
    }
    asm volatile("cp.async.commit_group;" ::: "memory");
}

__device__ __forceinline__ const float* pipe_adv(float* ring, int& ph, int& slot, int tx) {
    asm volatile("cp.async.wait_group 1;" ::: "memory");
    __syncthreads();
    int nh = ph + 2; if (nh >= 12) nh -= 12;
    kick(ring + ((slot + 2) % 3) * 8192, g_Wpk + nh*8192, tx);
    const float* cur = ring + slot * 8192;
    ph = (ph + 1 == 12) ? 0 : ph + 1;
    slot = (slot + 1) % 3;
    return cur;
}

// ---------------- GEMM building blocks (512 threads: 8 rows x 2 cols each) ----------------
__device__ __forceinline__ void ginit(u64 acc[8][2]) {
    #pragma unroll
    for (int i = 0; i < 8; i++) { acc[i][0] = 0ULL; acc[i][1] = 0ULL; }
}

__device__ __forceinline__ void gacc_h(u64 acc[8][2], const float* sA_,
                                       const float* sW_, int tx) {
    const int rg = tx >> 6;
    const int cg = tx & 63;
    const float* Wp = sW_ + cg*4;
    const float* Ap = sA_ + rg*8*128;
    #pragma unroll 4
    for (int k4 = 0; k4 < 16; k4++) {
        ulonglong2 wv0 = *reinterpret_cast<const ulonglong2*>(Wp + (2*k4)*256);
        ulonglong2 wv1 = *reinterpret_cast<const ulonglong2*>(Wp + (2*k4+1)*256);
        #pragma unroll
        for (int i = 0; i < 8; i++) {
            ulonglong2 av = *reinterpret_cast<const ulonglong2*>(Ap + i*128 + k4*4);
            acc[i][0] = fma2(av.x, wv0.x, acc[i][0]);
            acc[i][1] = fma2(av.x, wv0.y, acc[i][1]);
            acc[i][0] = fma2(av.y, wv1.x, acc[i][0]);
            acc[i][1] = fma2(av.y, wv1.y, acc[i][1]);
        }
    }
}

__device__ __forceinline__ void gepi(u64 acc[8][2], const float* sbias, bool relu,
                                     float* sC, int tx) {
    const int rg = tx >> 6, cg = tx & 63;
    float2 bz = *reinterpret_cast<const float2*>(sbias + cg*2);
    #pragma unroll
    for (int i = 0; i < 8; i++) {
        float lo, hi; float2 o;
        upk2(acc[i][0], lo, hi); o.x = lo + hi + bz.x;
        upk2(acc[i][1], lo, hi); o.y = lo + hi + bz.y;
        if (relu) { o.x = fmaxf(o.x, 0.f); o.y = fmaxf(o.y, 0.f); }
        *reinterpret_cast<float2*>(sC + (rg*8 + i)*128 + cg*2) = o;
    }
}

// ---------------- pairwise, h-pair version, fully barrier-free, in place on sB ----
// r[j][h] = mean_i relu(a[i][h] + b[j][h] + bias[h]) = 0.5/64 * (Sa + 64*v_j + sum_i |a_i + v_j|)
__device__ void pairwise_fn(const float* sA_, float* sB_, const float* sIB1, int tx) {
    const int hp = tx & 63;               // h-pair (2 channels via f32x2 lanes)
    const int jg = tx >> 6;               // 8 j-groups of 8
    const float* ab = sA_ + hp*2;
    float* bb = sB_ + jg*8*128 + hp*2;
    const u64 bias2 = *reinterpret_cast<const u64*>(sIB1 + hp*2);
    u64 vj[8], accj[8];
    #pragma unroll
    for (int t = 0; t < 8; t++) {         // preload v_j (own elements only -> in-place safe)
        vj[t] = add2(*reinterpret_cast<const u64*>(bb + t*128), bias2);
        accj[t] = 0ULL;
    }
    u64 Sa = 0ULL;
    const u64 MASK = 0x7FFFFFFF7FFFFFFFULL;
    #pragma unroll 1
    for (int pass = 0; pass < 2; pass++) {
        u64 ap[32];
        #pragma unroll
        for (int i = 0; i < 32; i++) {
            ap[i] = *reinterpret_cast<const u64*>(ab + (pass*32 + i)*128);
            Sa = add2(Sa, ap[i]);
        }
        #pragma unroll 1
        for (int t = 0; t < 8; t++) {
            u64 v = vj[t], s = accj[t];
            #pragma unroll
            for (int i = 0; i < 32; i++) {
                u64 x = add2(ap[i], v);
                x &= MASK;
                s = add2(s, x);
            }
            accj[t] = s;
        }
    }
    #pragma unroll
    for (int t = 0; t < 8; t++) {
        float slo, shi, alo, ahi, vlo, vhi;
        upk2(accj[t], slo, shi); upk2(Sa, alo, ahi); upk2(vj[t], vlo, vhi);
        float rlo = (alo + 64.f*vlo + slo) * (0.5f/64.f);
        float rhi = (ahi + 64.f*vhi + shi) * (0.5f/64.f);
        *reinterpret_cast<u64*>(bb + t*128) = pk2(rlo, rhi);
    }
}

// pred = Hd @ dec_w2 + db2 -> sP and global out
__device__ __forceinline__ void decf(const float* sHd, const float* sWdp, const float* sDB2,
                                     float* sP, float* __restrict__ out,
                                     int b, int step, int tx) {
    const int m = tx >> 3;
    const int d = tx & 7;
    u64 acc = 0ULL;
    const float* hp = sHd + m*128;
    const float* wp = sWdp + d*2;
    #pragma unroll 8
    for (int k2 = 0; k2 < 64; k2++)
        acc = fma2(*reinterpret_cast<const u64*>(hp + 2*k2),
                   *reinterpret_cast<const u64*>(wp + k2*16), acc);
    float lo, hi; upk2(acc, lo, hi);
    float val = lo + hi + sDB2[d];
    sP[m*8 + d] = val;
    out[((b*NST + step)*KS + m)*DD + d] = val;
}

// sO = relu(sP(64x8) @ We1(8x128) + eb1)
__device__ __forceinline__ void enc1(const float* sPin, const float* sWe1,
                                     const float* sEB1, float* sO, int tx) {
    const int r0 = (tx >> 6) * 8;
    const int c0 = (tx & 63) * 2;
    float2 w[8];
    #pragma unroll
    for (int k = 0; k < 8; k++) w[k] = *reinterpret_cast<const float2*>(sWe1 + k*128 + c0);
    float2 bz = *reinterpret_cast<const float2*>(sEB1 + c0);
    #pragma unroll
    for (int i = 0; i < 8; i++) {
        float2 o = bz;
        #pragma unroll
        for (int k = 0; k < 8; k++) {
            float a = sPin[(r0+i)*8 + k];
            o.x += a*w[k].x; o.y += a*w[k].y;
        }
        o.x = fmaxf(o.x, 0.f); o.y = fmaxf(o.y, 0.f);
        *reinterpret_cast<float2*>(sO + (r0+i)*128 + c0) = o;
    }
}

// ---------------- persistent per-batch rollout ----------------
__global__ __launch_bounds__(512, 1)
void rollout(const float* __restrict__ gt,
             const float* __restrict__ enc_w1, const float* __restrict__ enc_b1,
             const float* __restrict__ inter_b1,
             const float* __restrict__ dec_w2, const float* __restrict__ dec_b2,
             float* __restrict__ out) {
    extern __shared__ float sm[];
    float* sH   = sm + OFF_H;
    float* sA   = sm + OFF_A;
    float* sB   = sm + OFF_B;
    float* ring = sm + RNG0;
    float* sP   = sm + OFF_P;
    float* sWdp = sm + OFF_WDP;
    float* sWe1 = sm + OFF_WE1;

    const int tx = threadIdx.x;
    const int b  = blockIdx.x;

    #pragma unroll
    for (int t = 0; t < 2; t++) {
        int i = t*512 + tx;
        sWe1[i] = enc_w1[i];
        int k = i >> 3, d = i & 7;
        sWdp[(k >> 1)*16 + d*2 + (k & 1)] = dec_w2[i];
    }
    if (tx < 384) sm[OFF_BQ + tx] = g_bq[tx];
    if (tx < 128) {
        sm[OFF_B2  + tx] = g_b2[tx];
        sm[OFF_B3  + tx] = g_b3[tx];
        sm[OFF_EB1 + tx] = enc_b1[tx];
        sm[OFF_IB1 + tx] = inter_b1[tx];
    }
    if (tx < 8) sm[OFF_DB2 + tx] = dec_b2[tx];
    sP[tx] = gt[b*(TT*KS*DD) + tx];
    __syncthreads();

    enc1(sP, sWe1, sm + OFF_EB1, sH, tx);

    int ph = 0, slot = 0;
    kick(ring,        g_Wpk,        tx);
    kick(ring + 8192, g_Wpk + 8192, tx);

    #pragma unroll 1
    for (int step = 0; step < NST; step++) {
        const float* w;
        {   // a = He @ Wq_a + bq[128:256] -> sA
            u64 acc[8][2]; ginit(acc);
            w = pipe_adv(ring, ph, slot, tx); gacc_h(acc, sH,      w, tx);
            w = pipe_adv(ring, ph, slot, tx); gacc_h(acc, sH + 64, w, tx);
            gepi(acc, sm + OFF_BQ + 128, false, sA, tx);
        }
        {   // b = He @ Wq_b + bq[256:384] -> sB
            u64 acc[8][2]; ginit(acc);
            w = pipe_adv(ring, ph, slot, tx); gacc_h(acc, sH,      w, tx);
            w = pipe_adv(ring, ph, slot, tx); gacc_h(acc, sH + 64, w, tx);
            gepi(acc, sm + OFF_BQ + 256, false, sB, tx);
        }
        {   // pairwise (barrier-free, ordered by pipe_adv sync) + Hself
            w = pipe_adv(ring, ph, slot, tx);      // barrier: sA/sB visible
            pairwise_fn(sA, sB, sm + OFF_IB1, tx); // r -> sB in place
            u64 acc[8][2]; ginit(acc);
            gacc_h(acc, sH, w, tx);
            w = pipe_adv(ring, ph, slot, tx); gacc_h(acc, sH + 64, w, tx);
            gepi(acc, sm + OFF_BQ, true, sA, tx);  // Hself -> sA
        }
        {   // Hu = relu(Hself@W2a + r@W2b + b2) -> sH
            u64 acc[8][2]; ginit(acc);
            w = pipe_adv(ring, ph, slot, tx); gacc_h(acc, sA,      w, tx);
            w = pipe_adv(ring, ph, slot, tx); gacc_h(acc, sA + 64, w, tx);
            w = pipe_adv(ring, ph, slot, tx); gacc_h(acc, sB,      w, tx);
            w = pipe_adv(ring, ph, slot, tx); gacc_h(acc, sB + 64, w, tx);
            gepi(acc, sm + OFF_B2, true, sH, tx);
        }
        {   // Hd = relu(Hu@W3 + b3) -> sA
            u64 acc[8][2]; ginit(acc);
            w = pipe_adv(ring, ph, slot, tx); gacc_h(acc, sH,      w, tx);
            w = pipe_adv(ring, ph, slot, tx); gacc_h(acc, sH + 64, w, tx);
            gepi(acc, sm + OFF_B3, true, sA, tx);
        }
        __syncthreads();
        decf(sA, sWdp, sm + OFF_DB2, sP, out, b, step, tx);
        if (step + 1 < NST) {
            __syncthreads();
            enc1(sP, sWe1, sm + OFF_EB1, sH, tx);
        }
    }
    asm volatile("cp.async.wait_all;" ::: "memory");
}

// ---------------- launch ----------------
extern "C" void kernel_launch(void* const* d_in, const int* in_sizes, int n_in,
                              void* d_out, int out_size) {
    const float* gt       = (const float*)d_in[0];
    const float* enc_w1   = (const float*)d_in[2];
    const float* enc_b1   = (const float*)d_in[3];
    const float* enc_w2   = (const float*)d_in[4];
    const float* enc_b2   = (const float*)d_in[5];
    const float* self_w1  = (const float*)d_in[6];
    const float* self_b1  = (const float*)d_in[7];
    const float* self_w2  = (const float*)d_in[8];
    const float* self_b2  = (const float*)d_in[9];
    const float* inter_w1 = (const float*)d_in[10];
    const float* inter_b1 = (const float*)d_in[11];
    const float* inter_w2 = (const float*)d_in[12];
    const float* inter_b2 = (const float*)d_in[13];
    const float* upd_w1   = (const float*)d_in[14];
    const float* upd_b1   = (const float*)d_in[15];
    const float* upd_w2   = (const float*)d_in[16];
    const float* upd_b2   = (const float*)d_in[17];
    const float* dec_w1   = (const float*)d_in[18];
    const float* dec_b1   = (const float*)d_in[19];
    const float* dec_w2   = (const float*)d_in[20];
    const float* dec_b2   = (const float*)d_in[21];
    float* out = (float*)d_out;

    cudaFuncSetAttribute(rollout, cudaFuncAttributeMaxDynamicSharedMemorySize, SM_BYTES);

    prep<<<PB_TOTAL, 384>>>(gt, enc_w2, enc_b2, self_w1, self_b1, self_w2, self_b2,
                            inter_w1, inter_w2, inter_b2, upd_w1, upd_b1,
                            upd_w2, upd_b2, dec_w1, dec_b1, out);

    rollout<<<MB, 512, SM_BYTES>>>(gt, enc_w1, enc_b1, inter_b1, dec_w2, dec_b2, out);
}